// round 2
// baseline (speedup 1.0000x reference)
#include <cuda_runtime.h>
#include <math.h>

#define BB 4
#define SS 2048
#define DD 1024
#define FFD 4096
#define ROWS (BB*SS)   // 8192

// ---------------- scratch (device globals: no allocation) ----------------
__device__ float g_Q [ROWS*DD];
__device__ float g_K [ROWS*DD];
__device__ float g_V [ROWS*DD];
__device__ float g_S [(long)BB*SS*SS];   // 64 MB score scratch
__device__ float g_A [ROWS*DD];
__device__ float g_y1[ROWS*DD];
__device__ float g_y2[ROWS*DD];
__device__ float g_H [ROWS*FFD];

// ---------------- SGEMM: C = A * B (or A * B^T), 128x128x16 tiles ----------------
// A: [M,K] row-major.  B: NN -> [K,N] row-major, TB -> [N,K] row-major.
// CAUSAL: skip tiles fully above the diagonal (softmax never reads them).
template<bool TB, bool CAUSAL, bool BIAS, bool RELU>
__global__ void __launch_bounds__(256, 2)
sgemm_kernel(const float* __restrict__ A, const float* __restrict__ Bm,
             const float* __restrict__ bias, float* __restrict__ C,
             int M, int N, int K, float scale,
             long sA, long sB, long sC)
{
    const int bx = blockIdx.x, by = blockIdx.y;
    if (CAUSAL && bx > by) return;          // tile entirely above diagonal
    A  += (long)blockIdx.z * sA;
    Bm += (long)blockIdx.z * sB;
    C  += (long)blockIdx.z * sC;

    __shared__ __align__(16) float As[16][132];
    __shared__ __align__(16) float Bs[16][132];

    const int tx = threadIdx.x, ty = threadIdx.y;   // 16x16
    const int tid = ty * 16 + tx;
    const int m0 = by * 128, n0 = bx * 128;

    const int lr = tid >> 4;     // 0..15 (row group for A / B^T loads)
    const int lc = tid & 15;     // 0..15 (k within tile)
    const int br = tid >> 7;     // 0..1  (k row for NN B loads)
    const int bc = tid & 127;    // 0..127

    float acc[8][8];
    #pragma unroll
    for (int i = 0; i < 8; ++i)
        #pragma unroll
        for (int j = 0; j < 8; ++j) acc[i][j] = 0.0f;

    for (int k0 = 0; k0 < K; k0 += 16) {
        #pragma unroll
        for (int r = 0; r < 8; ++r) {
            int m = lr + r * 16;
            As[lc][m] = A[(long)(m0 + m) * K + (k0 + lc)];
        }
        if (TB) {
            #pragma unroll
            for (int r = 0; r < 8; ++r) {
                int n = lr + r * 16;
                Bs[lc][n] = Bm[(long)(n0 + n) * K + (k0 + lc)];
            }
        } else {
            #pragma unroll
            for (int r = 0; r < 8; ++r) {
                int kk = br + r * 2;
                Bs[kk][bc] = Bm[(long)(k0 + kk) * N + (n0 + bc)];
            }
        }
        __syncthreads();

        #pragma unroll
        for (int kk = 0; kk < 16; ++kk) {
            float4 a0 = *(const float4*)&As[kk][ty * 8];
            float4 a1 = *(const float4*)&As[kk][ty * 8 + 4];
            float4 b0 = *(const float4*)&Bs[kk][tx * 8];
            float4 b1 = *(const float4*)&Bs[kk][tx * 8 + 4];
            float a[8] = {a0.x, a0.y, a0.z, a0.w, a1.x, a1.y, a1.z, a1.w};
            float b[8] = {b0.x, b0.y, b0.z, b0.w, b1.x, b1.y, b1.z, b1.w};
            #pragma unroll
            for (int i = 0; i < 8; ++i)
                #pragma unroll
                for (int j = 0; j < 8; ++j)
                    acc[i][j] = fmaf(a[i], b[j], acc[i][j]);
        }
        __syncthreads();
    }

    #pragma unroll
    for (int i = 0; i < 8; ++i) {
        long row = m0 + ty * 8 + i;
        float out[8];
        #pragma unroll
        for (int j = 0; j < 8; ++j) {
            float v = acc[i][j] * scale;
            if (BIAS) v += bias[n0 + tx * 8 + j];
            if (RELU) v = fmaxf(v, 0.0f);
            out[j] = v;
        }
        *(float4*)&C[row * (long)N + n0 + tx * 8]     = *(float4*)&out[0];
        *(float4*)&C[row * (long)N + n0 + tx * 8 + 4] = *(float4*)&out[4];
    }
}

// ---------------- row softmax (optionally causal); writes 0 in masked tail ----------------
__global__ void softmax_kernel(float* __restrict__ S, int Sq, int Sk, int causal)
{
    const long row = blockIdx.x;                 // b*Sq + q
    const int  q   = (int)(row % Sq);
    const int  valid = causal ? (q + 1) : Sk;
    float* p = S + row * (long)Sk;
    const int tid = threadIdx.x;
    __shared__ float red[256];

    float m = -3.0e38f;
    for (int k = tid; k < valid; k += 256) m = fmaxf(m, p[k]);
    red[tid] = m; __syncthreads();
    for (int st = 128; st > 0; st >>= 1) {
        if (tid < st) red[tid] = fmaxf(red[tid], red[tid + st]);
        __syncthreads();
    }
    m = red[0]; __syncthreads();

    float s = 0.0f;
    for (int k = tid; k < valid; k += 256) s += __expf(p[k] - m);
    red[tid] = s; __syncthreads();
    for (int st = 128; st > 0; st >>= 1) {
        if (tid < st) red[tid] += red[tid + st];
        __syncthreads();
    }
    const float inv = 1.0f / red[0];

    for (int k = tid; k < Sk; k += 256) {
        float val = (k < valid) ? __expf(p[k] - m) * inv : 0.0f;
        p[k] = val;
    }
}

// ---------------- out = LayerNorm(R + X) * gamma + beta ----------------
__global__ void add_ln_kernel(const float* __restrict__ R, const float* __restrict__ X,
                              const float* __restrict__ g, const float* __restrict__ b,
                              float* __restrict__ O)
{
    const int  tid = threadIdx.x;        // 256 threads, 4 floats each (D=1024)
    const long row = blockIdx.x;
    const float4 rv = ((const float4*)(R + row * DD))[tid];
    const float4 xv = ((const float4*)(X + row * DD))[tid];
    float v[4] = {rv.x + xv.x, rv.y + xv.y, rv.z + xv.z, rv.w + xv.w};

    float s  = v[0] + v[1] + v[2] + v[3];
    float sq = v[0]*v[0] + v[1]*v[1] + v[2]*v[2] + v[3]*v[3];
    __shared__ float rs[256], rq[256];
    rs[tid] = s; rq[tid] = sq; __syncthreads();
    for (int st = 128; st > 0; st >>= 1) {
        if (tid < st) { rs[tid] += rs[tid + st]; rq[tid] += rq[tid + st]; }
        __syncthreads();
    }
    const float mu  = rs[0] * (1.0f / DD);
    const float var = rq[0] * (1.0f / DD) - mu * mu;
    const float inv = rsqrtf(var + 1e-5f);

    const float4 gv = ((const float4*)g)[tid];
    const float4 bv = ((const float4*)b)[tid];
    float4 o;
    o.x = (v[0] - mu) * inv * gv.x + bv.x;
    o.y = (v[1] - mu) * inv * gv.y + bv.y;
    o.z = (v[2] - mu) * inv * gv.z + bv.z;
    o.w = (v[3] - mu) * inv * gv.w + bv.w;
    ((float4*)(O + row * DD))[tid] = o;
}

// ---------------- launch ----------------
extern "C" void kernel_launch(void* const* d_in, const int* in_sizes, int n_in,
                              void* d_out, int out_size)
{
    (void)in_sizes; (void)n_in; (void)out_size;
    const float* y    = (const float*)d_in[0];
    const float* Z    = (const float*)d_in[1];
    const float* WQ1  = (const float*)d_in[2];
    const float* WK1  = (const float*)d_in[3];
    const float* WV1  = (const float*)d_in[4];
    const float* WQ2  = (const float*)d_in[5];
    const float* WK2  = (const float*)d_in[6];
    const float* WV2  = (const float*)d_in[7];
    const float* Wff1 = (const float*)d_in[8];
    const float* bff1 = (const float*)d_in[9];
    const float* Wff2 = (const float*)d_in[10];
    const float* bff2 = (const float*)d_in[11];
    const float* g1   = (const float*)d_in[12];
    const float* be1  = (const float*)d_in[13];
    const float* g2   = (const float*)d_in[14];
    const float* be2  = (const float*)d_in[15];
    const float* g3   = (const float*)d_in[16];
    const float* be3  = (const float*)d_in[17];
    float* out = (float*)d_out;

    float *Q, *Kp, *V, *Sc, *At, *y1, *y2, *H;
    cudaGetSymbolAddress((void**)&Q,  g_Q);
    cudaGetSymbolAddress((void**)&Kp, g_K);
    cudaGetSymbolAddress((void**)&V,  g_V);
    cudaGetSymbolAddress((void**)&Sc, g_S);
    cudaGetSymbolAddress((void**)&At, g_A);
    cudaGetSymbolAddress((void**)&y1, g_y1);
    cudaGetSymbolAddress((void**)&y2, g_y2);
    cudaGetSymbolAddress((void**)&H,  g_H);

    const dim3 th(16, 16);
    const dim3 gProj(DD / 128, ROWS / 128);           // (8, 64)
    const dim3 gScore(SS / 128, SS / 128, BB);        // (16, 16, 4)
    const dim3 gAttnV(DD / 128, SS / 128, BB);        // (8, 16, 4)
    const float ascale = 1.0f / 32.0f;                // 1/sqrt(1024)
    const long sQK = (long)SS * DD;
    const long sSc = (long)SS * SS;

    // ---- block 1: causal self-attention + add&norm ----
    sgemm_kernel<false,false,false,false><<<gProj, th>>>(y, WQ1, nullptr, Q,  ROWS, DD, DD, 1.0f, 0, 0, 0);
    sgemm_kernel<false,false,false,false><<<gProj, th>>>(y, WK1, nullptr, Kp, ROWS, DD, DD, 1.0f, 0, 0, 0);
    sgemm_kernel<false,false,false,false><<<gProj, th>>>(y, WV1, nullptr, V,  ROWS, DD, DD, 1.0f, 0, 0, 0);
    sgemm_kernel<true, true, false,false><<<gScore, th>>>(Q, Kp, nullptr, Sc, SS, SS, DD, ascale, sQK, sQK, sSc);
    softmax_kernel<<<BB * SS, 256>>>(Sc, SS, SS, 1);
    sgemm_kernel<false,false,false,false><<<gAttnV, th>>>(Sc, V, nullptr, At, SS, DD, SS, 1.0f, sSc, sQK, sQK);
    add_ln_kernel<<<ROWS, 256>>>(y, At, g1, be1, y1);

    // ---- block 2: cross-attention + add&norm ----
    sgemm_kernel<false,false,false,false><<<gProj, th>>>(y1, WQ2, nullptr, Q,  ROWS, DD, DD, 1.0f, 0, 0, 0);
    sgemm_kernel<false,false,false,false><<<gProj, th>>>(Z,  WK2, nullptr, Kp, ROWS, DD, DD, 1.0f, 0, 0, 0);
    sgemm_kernel<false,false,false,false><<<gProj, th>>>(Z,  WV2, nullptr, V,  ROWS, DD, DD, 1.0f, 0, 0, 0);
    sgemm_kernel<true,false,false,false><<<gScore, th>>>(Q, Kp, nullptr, Sc, SS, SS, DD, ascale, sQK, sQK, sSc);
    softmax_kernel<<<BB * SS, 256>>>(Sc, SS, SS, 0);
    sgemm_kernel<false,false,false,false><<<gAttnV, th>>>(Sc, V, nullptr, At, SS, DD, SS, 1.0f, sSc, sQK, sQK);
    add_ln_kernel<<<ROWS, 256>>>(y1, At, g2, be2, y2);

    // ---- FFN + add&norm ----
    sgemm_kernel<false,false,true, true ><<<dim3(FFD / 128, ROWS / 128), th>>>(y2, Wff1, bff1, H,  ROWS, FFD, DD,  1.0f, 0, 0, 0);
    sgemm_kernel<false,false,true, false><<<dim3(DD  / 128, ROWS / 128), th>>>(H,  Wff2, bff2, At, ROWS, DD,  FFD, 1.0f, 0, 0, 0);
    add_ln_kernel<<<ROWS, 256>>>(y2, At, g3, be3, out);
}

// round 4
// speedup vs baseline: 3.0065x; 3.0065x over previous
#include <cuda_runtime.h>
#include <math.h>
#include <stdint.h>

#define BB 4
#define SS 2048
#define DD 1024
#define FFD 4096
#define ROWS (BB*SS)   // 8192

// ---------------- scratch (device globals: no allocation) ----------------
__device__ float g_Q [ROWS*DD];
__device__ float g_K [ROWS*DD];
__device__ float g_V [ROWS*DD];
__device__ float g_S [(long)BB*SS*SS];   // 64 MB score scratch
__device__ float g_A [ROWS*DD];
__device__ float g_y1[ROWS*DD];
__device__ float g_y2[ROWS*DD];
__device__ float g_H [ROWS*FFD];

// ---------------- helpers ----------------
__device__ __forceinline__ uint32_t f2tf32(float x) {
    uint32_t u;
    asm("cvt.rna.tf32.f32 %0, %1;" : "=r"(u) : "f"(x));
    return u;
}
__device__ __forceinline__ uint4 f4tf32(float4 v) {
    uint4 u; u.x = f2tf32(v.x); u.y = f2tf32(v.y); u.z = f2tf32(v.z); u.w = f2tf32(v.w);
    return u;
}
__device__ __forceinline__ void mma_tf32(float (&d)[4], const uint32_t (&a)[4], const uint32_t (&b)[2]) {
    asm volatile("mma.sync.aligned.m16n8k8.row.col.f32.tf32.tf32.f32 "
                 "{%0,%1,%2,%3}, {%4,%5,%6,%7}, {%8,%9}, {%0,%1,%2,%3};"
                 : "+f"(d[0]), "+f"(d[1]), "+f"(d[2]), "+f"(d[3])
                 : "r"(a[0]), "r"(a[1]), "r"(a[2]), "r"(a[3]), "r"(b[0]), "r"(b[1]));
}

// smem: per buffer, A[128][36] then B[128][36] floats (stride 36 => 144B rows, 16B aligned)
#define STRIDE 36
#define ABUF   (128*STRIDE)           // 4608 floats
#define BUFSZ  (2*ABUF)               // 9216 floats per stage
#define SMEM_BYTES (2*BUFSZ*4)        // 73728

// ---- stage loaders (gmem -> regs) and storers (regs -> smem) ----
__device__ __forceinline__ void ldg_rowk(const float* __restrict__ P, int r0, int k0, int ld,
                                         int tid, uint4 st[4]) {
    // 128 rows x 32 k, float4 along k. pos: row=pos>>3, kq=pos&7
    #pragma unroll
    for (int i = 0; i < 4; ++i) {
        int pos = tid + i * 256;
        int row = pos >> 3, kq = pos & 7;
        float4 v = *(const float4*)&P[(long)(r0 + row) * ld + k0 + kq * 4];
        st[i] = f4tf32(v);
    }
}
__device__ __forceinline__ void sts_rowk(float* __restrict__ S, int tid, const uint4 st[4]) {
    #pragma unroll
    for (int i = 0; i < 4; ++i) {
        int pos = tid + i * 256;
        int row = pos >> 3, kq = pos & 7;
        *(uint4*)&S[row * STRIDE + kq * 4] = st[i];
    }
}
__device__ __forceinline__ void ldg_nn(const float* __restrict__ Bm, int n0, int k0, int N,
                                       int tid, uint4 st[4]) {
    // B is [K,N] row-major; gather 4 k per thread at fixed n. pos: n=pos&127, kq=pos>>7
    #pragma unroll
    for (int i = 0; i < 4; ++i) {
        int pos = tid + i * 256;
        int n = pos & 127, kq = pos >> 7;
        const float* p = &Bm[(long)(k0 + kq * 4) * N + n0 + n];
        float4 v;
        v.x = p[0]; v.y = p[N]; v.z = p[2 * (long)N]; v.w = p[3 * (long)N];
        st[i] = f4tf32(v);
    }
}
__device__ __forceinline__ void sts_nn(float* __restrict__ S, int tid, const uint4 st[4]) {
    #pragma unroll
    for (int i = 0; i < 4; ++i) {
        int pos = tid + i * 256;
        int n = pos & 127, kq = pos >> 7;
        *(uint4*)&S[n * STRIDE + kq * 4] = st[i];
    }
}

// ---------------- tf32 HMMA GEMM: C[M,N] = A[M,K] * B, tile 128x128xK32 ----------------
// TB: B is [N,K] row-major (C = A*B^T). else B is [K,N] row-major.
// CAUSAL: skip tiles fully above diagonal. CLIPK: K-loop stops at m0+128 (causal probs).
template<bool TB, bool CAUSAL, bool BIAS, bool RELU, bool CLIPK>
__global__ void __launch_bounds__(256, 2)
tgemm(const float* __restrict__ A, const float* __restrict__ Bm,
      const float* __restrict__ bias, float* __restrict__ C,
      int N, int K, float scale, long sA, long sB, long sC)
{
    const int m0 = blockIdx.y * 128, n0 = blockIdx.x * 128;
    if (CAUSAL && n0 > m0 + 127) return;
    A  += (long)blockIdx.z * sA;
    Bm += (long)blockIdx.z * sB;
    C  += (long)blockIdx.z * sC;

    extern __shared__ __align__(16) float sm[];
    const int tid = threadIdx.x, lane = tid & 31, wid = tid >> 5;
    const int wm = (wid & 1) * 64;        // warp row offset (2 warps in M)
    const int wn = (wid >> 1) * 32;       // warp col offset (4 warps in N)
    const int gid = lane >> 2, tg = lane & 3;

    int Keff = K;
    if (CLIPK) { int km = m0 + 128; Keff = (km < K) ? km : K; }
    const int nch = Keff >> 5;

    float acc[4][4][4];
    #pragma unroll
    for (int mt = 0; mt < 4; ++mt)
        #pragma unroll
        for (int nt = 0; nt < 4; ++nt)
            #pragma unroll
            for (int j = 0; j < 4; ++j) acc[mt][nt][j] = 0.0f;

    uint4 sa[4], sb[4];
    // prologue: chunk 0 -> buf 0
    ldg_rowk(A, m0, 0, K, tid, sa);
    if (TB) ldg_rowk(Bm, n0, 0, K, tid, sb); else ldg_nn(Bm, n0, 0, N, tid, sb);
    sts_rowk(sm, tid, sa);
    if (TB) sts_rowk(sm + ABUF, tid, sb); else sts_nn(sm + ABUF, tid, sb);
    __syncthreads();

    for (int c = 0; c < nch; ++c) {
        const int s = c & 1;
        const float* As = sm + s * BUFSZ;
        const float* Bs = As + ABUF;
        const bool more = (c + 1 < nch);
        if (more) {
            const int k0 = (c + 1) << 5;
            ldg_rowk(A, m0, k0, K, tid, sa);
            if (TB) ldg_rowk(Bm, n0, k0, K, tid, sb); else ldg_nn(Bm, n0, k0, N, tid, sb);
        }
        // compute chunk c (4 k-steps of 8)
        #pragma unroll
        for (int kk = 0; kk < 4; ++kk) {
            const int kb = kk * 8;
            uint32_t b[4][2];
            #pragma unroll
            for (int nt = 0; nt < 4; ++nt) {
                const int nb = (wn + nt * 8 + gid) * STRIDE + kb + tg;
                b[nt][0] = __float_as_uint(Bs[nb]);
                b[nt][1] = __float_as_uint(Bs[nb + 4]);
            }
            #pragma unroll
            for (int mt = 0; mt < 4; ++mt) {
                uint32_t a[4];
                const int rm = (wm + mt * 16 + gid) * STRIDE + kb + tg;
                a[0] = __float_as_uint(As[rm]);
                a[1] = __float_as_uint(As[rm + 8 * STRIDE]);
                a[2] = __float_as_uint(As[rm + 4]);
                a[3] = __float_as_uint(As[rm + 8 * STRIDE + 4]);
                #pragma unroll
                for (int nt = 0; nt < 4; ++nt) mma_tf32(acc[mt][nt], a, b[nt]);
            }
        }
        if (more) {
            float* An = sm + ((c + 1) & 1) * BUFSZ;
            sts_rowk(An, tid, sa);
            if (TB) sts_rowk(An + ABUF, tid, sb); else sts_nn(An + ABUF, tid, sb);
        }
        __syncthreads();
    }

    // ---- epilogue: acc -> C ----
    #pragma unroll
    for (int mt = 0; mt < 4; ++mt) {
        const long r0 = m0 + wm + mt * 16 + gid;
        #pragma unroll
        for (int nt = 0; nt < 4; ++nt) {
            const int col = n0 + wn + nt * 8 + 2 * tg;
            float v0 = acc[mt][nt][0] * scale;
            float v1 = acc[mt][nt][1] * scale;
            float v2 = acc[mt][nt][2] * scale;
            float v3 = acc[mt][nt][3] * scale;
            if (BIAS) {
                float b0 = bias[col], b1 = bias[col + 1];
                v0 += b0; v1 += b1; v2 += b0; v3 += b1;
            }
            if (RELU) {
                v0 = fmaxf(v0, 0.0f); v1 = fmaxf(v1, 0.0f);
                v2 = fmaxf(v2, 0.0f); v3 = fmaxf(v3, 0.0f);
            }
            float2 p0 = make_float2(v0, v1), p1 = make_float2(v2, v3);
            *(float2*)&C[r0 * (long)N + col]       = p0;
            *(float2*)&C[(r0 + 8) * (long)N + col] = p1;
        }
    }
}

// ---------------- row softmax (optionally causal); writes 0 in masked tail ----------------
__global__ void softmax_kernel(float* __restrict__ S, int Sq, int Sk, int causal)
{
    const long row = blockIdx.x;
    const int  q   = (int)(row % Sq);
    const int  valid = causal ? (q + 1) : Sk;
    float* p = S + row * (long)Sk;
    const int tid = threadIdx.x;
    __shared__ float red[256];

    float m = -3.0e38f;
    for (int k = tid; k < valid; k += 256) m = fmaxf(m, p[k]);
    red[tid] = m; __syncthreads();
    for (int st = 128; st > 0; st >>= 1) {
        if (tid < st) red[tid] = fmaxf(red[tid], red[tid + st]);
        __syncthreads();
    }
    m = red[0]; __syncthreads();

    float s = 0.0f;
    for (int k = tid; k < valid; k += 256) s += __expf(p[k] - m);
    red[tid] = s; __syncthreads();
    for (int st = 128; st > 0; st >>= 1) {
        if (tid < st) red[tid] += red[tid + st];
        __syncthreads();
    }
    const float inv = 1.0f / red[0];

    for (int k = tid; k < Sk; k += 256) {
        float val = (k < valid) ? __expf(p[k] - m) * inv : 0.0f;
        p[k] = val;
    }
}

// ---------------- out = LayerNorm(R + X) * gamma + beta ----------------
__global__ void add_ln_kernel(const float* __restrict__ R, const float* __restrict__ X,
                              const float* __restrict__ g, const float* __restrict__ b,
                              float* __restrict__ O)
{
    const int  tid = threadIdx.x;
    const long row = blockIdx.x;
    const float4 rv = ((const float4*)(R + row * DD))[tid];
    const float4 xv = ((const float4*)(X + row * DD))[tid];
    float v[4] = {rv.x + xv.x, rv.y + xv.y, rv.z + xv.z, rv.w + xv.w};

    float s  = v[0] + v[1] + v[2] + v[3];
    float sq = v[0]*v[0] + v[1]*v[1] + v[2]*v[2] + v[3]*v[3];
    __shared__ float rs[256], rq[256];
    rs[tid] = s; rq[tid] = sq; __syncthreads();
    for (int st = 128; st > 0; st >>= 1) {
        if (tid < st) { rs[tid] += rs[tid + st]; rq[tid] += rq[tid + st]; }
        __syncthreads();
    }
    const float mu  = rs[0] * (1.0f / DD);
    const float var = rq[0] * (1.0f / DD) - mu * mu;
    const float inv = rsqrtf(var + 1e-5f);

    const float4 gv = ((const float4*)g)[tid];
    const float4 bv = ((const float4*)b)[tid];
    float4 o;
    o.x = (v[0] - mu) * inv * gv.x + bv.x;
    o.y = (v[1] - mu) * inv * gv.y + bv.y;
    o.z = (v[2] - mu) * inv * gv.z + bv.z;
    o.w = (v[3] - mu) * inv * gv.w + bv.w;
    ((float4*)(O + row * DD))[tid] = o;
}

// ---------------- launch ----------------
extern "C" void kernel_launch(void* const* d_in, const int* in_sizes, int n_in,
                              void* d_out, int out_size)
{
    (void)in_sizes; (void)n_in; (void)out_size;
    const float* y    = (const float*)d_in[0];
    const float* Z    = (const float*)d_in[1];
    const float* WQ1  = (const float*)d_in[2];
    const float* WK1  = (const float*)d_in[3];
    const float* WV1  = (const float*)d_in[4];
    const float* WQ2  = (const float*)d_in[5];
    const float* WK2  = (const float*)d_in[6];
    const float* WV2  = (const float*)d_in[7];
    const float* Wff1 = (const float*)d_in[8];
    const float* bff1 = (const float*)d_in[9];
    const float* Wff2 = (const float*)d_in[10];
    const float* bff2 = (const float*)d_in[11];
    const float* g1   = (const float*)d_in[12];
    const float* be1  = (const float*)d_in[13];
    const float* g2   = (const float*)d_in[14];
    const float* be2  = (const float*)d_in[15];
    const float* g3   = (const float*)d_in[16];
    const float* be3  = (const float*)d_in[17];
    float* out = (float*)d_out;

    float *Q, *Kp, *V, *Sc, *At, *y1, *y2, *H;
    cudaGetSymbolAddress((void**)&Q,  g_Q);
    cudaGetSymbolAddress((void**)&Kp, g_K);
    cudaGetSymbolAddress((void**)&V,  g_V);
    cudaGetSymbolAddress((void**)&Sc, g_S);
    cudaGetSymbolAddress((void**)&At, g_A);
    cudaGetSymbolAddress((void**)&y1, g_y1);
    cudaGetSymbolAddress((void**)&y2, g_y2);
    cudaGetSymbolAddress((void**)&H,  g_H);

    cudaFuncSetAttribute(tgemm<false,false,false,false,false>, cudaFuncAttributeMaxDynamicSharedMemorySize, SMEM_BYTES);
    cudaFuncSetAttribute(tgemm<true, true, false,false,false>, cudaFuncAttributeMaxDynamicSharedMemorySize, SMEM_BYTES);
    cudaFuncSetAttribute(tgemm<true, false,false,false,false>, cudaFuncAttributeMaxDynamicSharedMemorySize, SMEM_BYTES);
    cudaFuncSetAttribute(tgemm<false,false,false,false,true >, cudaFuncAttributeMaxDynamicSharedMemorySize, SMEM_BYTES);
    cudaFuncSetAttribute(tgemm<false,false,true, true, false>, cudaFuncAttributeMaxDynamicSharedMemorySize, SMEM_BYTES);
    cudaFuncSetAttribute(tgemm<false,false,true, false,false>, cudaFuncAttributeMaxDynamicSharedMemorySize, SMEM_BYTES);

    const dim3 th(256);
    const dim3 gProj(DD / 128, ROWS / 128);            // (8, 64)
    const dim3 gScore(SS / 128, SS / 128, BB);         // (16, 16, 4)
    const dim3 gAttnV(DD / 128, SS / 128, BB);         // (8, 16, 4)
    const dim3 gFF1(FFD / 128, ROWS / 128);            // (32, 64)
    const dim3 gFF2(DD / 128, ROWS / 128);             // (8, 64)
    const float ascale = 1.0f / 32.0f;                 // 1/sqrt(1024)
    const long sQK = (long)SS * DD;
    const long sSc = (long)SS * SS;

    // ---- block 1: causal self-attention + add&norm ----
    tgemm<false,false,false,false,false><<<gProj, th, SMEM_BYTES>>>(y, WQ1, nullptr, Q,  DD, DD, 1.0f, 0, 0, 0);
    tgemm<false,false,false,false,false><<<gProj, th, SMEM_BYTES>>>(y, WK1, nullptr, Kp, DD, DD, 1.0f, 0, 0, 0);
    tgemm<false,false,false,false,false><<<gProj, th, SMEM_BYTES>>>(y, WV1, nullptr, V,  DD, DD, 1.0f, 0, 0, 0);
    tgemm<true, true, false,false,false><<<gScore, th, SMEM_BYTES>>>(Q, Kp, nullptr, Sc, SS, DD, ascale, sQK, sQK, sSc);
    softmax_kernel<<<BB * SS, 256>>>(Sc, SS, SS, 1);
    tgemm<false,false,false,false,true ><<<gAttnV, th, SMEM_BYTES>>>(Sc, V, nullptr, At, DD, SS, 1.0f, sSc, sQK, sQK);
    add_ln_kernel<<<ROWS, 256>>>(y, At, g1, be1, y1);

    // ---- block 2: cross-attention + add&norm ----
    tgemm<false,false,false,false,false><<<gProj, th, SMEM_BYTES>>>(y1, WQ2, nullptr, Q,  DD, DD, 1.0f, 0, 0, 0);
    tgemm<false,false,false,false,false><<<gProj, th, SMEM_BYTES>>>(Z,  WK2, nullptr, Kp, DD, DD, 1.0f, 0, 0, 0);
    tgemm<false,false,false,false,false><<<gProj, th, SMEM_BYTES>>>(Z,  WV2, nullptr, V,  DD, DD, 1.0f, 0, 0, 0);
    tgemm<true, false,false,false,false><<<gScore, th, SMEM_BYTES>>>(Q, Kp, nullptr, Sc, SS, DD, ascale, sQK, sQK, sSc);
    softmax_kernel<<<BB * SS, 256>>>(Sc, SS, SS, 0);
    tgemm<false,false,false,false,false><<<gAttnV, th, SMEM_BYTES>>>(Sc, V, nullptr, At, DD, SS, 1.0f, sSc, sQK, sQK);
    add_ln_kernel<<<ROWS, 256>>>(y1, At, g2, be2, y2);

    // ---- FFN + add&norm ----
    tgemm<false,false,true, true, false><<<gFF1, th, SMEM_BYTES>>>(y2, Wff1, bff1, H,  FFD, DD,  1.0f, 0, 0, 0);
    tgemm<false,false,true, false,false><<<gFF2, th, SMEM_BYTES>>>(H,  Wff2, bff2, At, DD,  FFD, 1.0f, 0, 0, 0);
    add_ln_kernel<<<ROWS, 256>>>(y2, At, g3, be3, out);
}

// round 6
// speedup vs baseline: 3.6032x; 1.1985x over previous
#include <cuda_runtime.h>
#include <math.h>
#include <stdint.h>

#define BB 4
#define SS 2048
#define DD 1024
#define FFD 4096
#define ROWS (BB*SS)   // 8192
#define DSQ (DD*DD)
#define RD  (ROWS*DD)

// ---------------- scratch (device globals: no allocation) ----------------
__device__ float g_W  [6*DSQ];       // tf32-rounded WQ1,WK1,WV1,WQ2,WK2,WV2
__device__ float g_Wf1[DD*FFD];
__device__ float g_Wf2[FFD*DD];
__device__ float g_yc [RD];          // tf32-rounded y
__device__ float g_Zc [RD];          // tf32-rounded Z
__device__ float g_QKV[3*RD];        // Q,K,V (rounded at epilogue)
__device__ float g_S  [(long)BB*SS*SS];   // 64 MB score scratch
__device__ float g_At [RD];
__device__ float g_y1 [RD];
__device__ float g_y2 [RD];
__device__ float g_H  [ROWS*FFD];

// ---------------- helpers ----------------
__device__ __forceinline__ uint32_t smem_u32(const void* p) {
    uint32_t a;
    asm("{ .reg .u64 t; cvta.to.shared.u64 t, %1; cvt.u32.u64 %0, t; }" : "=r"(a) : "l"(p));
    return a;
}
__device__ __forceinline__ float f2tf32f(float x) {
    uint32_t u;
    asm("cvt.rna.tf32.f32 %0, %1;" : "=r"(u) : "f"(x));
    return __uint_as_float(u);
}
__device__ __forceinline__ void mma_tf32(float (&d)[4], const uint32_t (&a)[4], const uint32_t (&b)[2]) {
    asm volatile("mma.sync.aligned.m16n8k8.row.col.f32.tf32.tf32.f32 "
                 "{%0,%1,%2,%3}, {%4,%5,%6,%7}, {%8,%9}, {%0,%1,%2,%3};"
                 : "+f"(d[0]), "+f"(d[1]), "+f"(d[2]), "+f"(d[3])
                 : "r"(a[0]), "r"(a[1]), "r"(a[2]), "r"(a[3]), "r"(b[0]), "r"(b[1]));
}
#define CP16(dst, src) asm volatile("cp.async.cg.shared.global [%0], [%1], 16;" :: "r"(dst), "l"(src))
#define CP_COMMIT()    asm volatile("cp.async.commit_group;" ::: "memory")
#define CP_WAIT(n)     asm volatile("cp.async.wait_group %0;" :: "n"(n) : "memory")

// smem layout (floats): per stage A[128][36] then B (TB: [256][36], NN: [32][264])
#define STRIDE_A  36
#define STRIDE_BT 36
#define STRIDE_BN 264
#define A_FLOATS  (128*STRIDE_A)       // 4608
#define B_FLOATS  9216                 // max(256*36, 32*264)
#define STAGE_FLOATS (A_FLOATS + B_FLOATS)
#define SMEM_BYTES (3*STAGE_FLOATS*4)  // 165888

template<bool TB>
__device__ __forceinline__ void issue_stage(uint32_t sA, uint32_t sB,
    const float* __restrict__ A, const float* __restrict__ Bm,
    int m0, int n0, int k0, int N, int K, int tid)
{
    #pragma unroll
    for (int i = 0; i < 4; ++i) {            // A: 128 rows x 8 k-quads
        int pos = tid + i * 256;
        int row = pos >> 3, kq = pos & 7;
        CP16(sA + (uint32_t)(row * STRIDE_A + kq * 4) * 4,
             &A[(long)(m0 + row) * K + k0 + kq * 4]);
    }
    if (TB) {
        #pragma unroll
        for (int i = 0; i < 8; ++i) {        // B: 256 rows x 8 k-quads
            int pos = tid + i * 256;
            int row = pos >> 3, kq = pos & 7;
            CP16(sB + (uint32_t)(row * STRIDE_BT + kq * 4) * 4,
                 &Bm[(long)(n0 + row) * K + k0 + kq * 4]);
        }
    } else {
        #pragma unroll
        for (int i = 0; i < 8; ++i) {        // B: 32 k-rows x 64 n-quads
            int pos = tid + i * 256;
            int k = pos >> 6, nq = pos & 63;
            CP16(sB + (uint32_t)(k * STRIDE_BN + nq * 4) * 4,
                 &Bm[(long)(k0 + k) * N + n0 + nq * 4]);
        }
    }
    CP_COMMIT();
}

// ---------------- tf32 HMMA GEMM: C[M,N] = A[M,K]*B, tile 128x256xK32, 8 warps ----
// TB: B is [N,K] (C=A*B^T). CAUSAL: skip tiles above diagonal. CLIPK: K stops at m0+128.
// ROUND: write tf32-rounded output (it feeds another GEMM).
template<bool TB, bool CAUSAL, bool BIAS, bool RELU, bool CLIPK, bool ROUND>
__global__ void __launch_bounds__(256, 1)
tgemm(const float* __restrict__ A, const float* __restrict__ Bm,
      const float* __restrict__ bias, float* __restrict__ C,
      int N, int K, float scale, long sA_, long sB_, long sC_)
{
    const int m0 = blockIdx.y * 128, n0 = blockIdx.x * 256;
    if (CAUSAL && n0 > m0 + 127) return;
    A  += (long)blockIdx.z * sA_;
    Bm += (long)blockIdx.z * sB_;
    C  += (long)blockIdx.z * sC_;

    extern __shared__ __align__(16) float sm[];
    const uint32_t sb = smem_u32(sm);
    const int tid = threadIdx.x, lane = tid & 31, wid = tid >> 5;
    const int wm = (wid & 1) * 64;          // 2 warps in M
    const int wn = (wid >> 1) * 64;         // 4 warps in N
    const int gid = lane >> 2, tg = lane & 3;

    int Keff = K;
    if (CLIPK) { int km = m0 + 128; Keff = (km < K) ? km : K; }
    const int nch = Keff >> 5;

    float acc[4][8][4];
    #pragma unroll
    for (int mt = 0; mt < 4; ++mt)
        #pragma unroll
        for (int nt = 0; nt < 8; ++nt)
            #pragma unroll
            for (int j = 0; j < 4; ++j) acc[mt][nt][j] = 0.0f;

    const uint32_t stB = (uint32_t)STAGE_FLOATS * 4;
    issue_stage<TB>(sb, sb + A_FLOATS * 4, A, Bm, m0, n0, 0, N, K, tid);
    if (nch > 1)
        issue_stage<TB>(sb + stB, sb + stB + A_FLOATS * 4, A, Bm, m0, n0, 32, N, K, tid);

    for (int c = 0; c < nch; ++c) {
        if (c + 2 <= nch) CP_WAIT(1); else CP_WAIT(0);
        __syncthreads();
        if (c + 2 < nch) {
            const uint32_t off = (uint32_t)((c + 2) % 3) * stB;
            issue_stage<TB>(sb + off, sb + off + A_FLOATS * 4, A, Bm, m0, n0, (c + 2) << 5, N, K, tid);
        }
        const float* As = sm + (c % 3) * STAGE_FLOATS;
        const float* Bs = As + A_FLOATS;

        #pragma unroll
        for (int kk = 0; kk < 4; ++kk) {
            const int kb = kk * 8;
            uint32_t b[8][2];
            #pragma unroll
            for (int nt = 0; nt < 8; ++nt) {
                if (TB) {
                    const int ib = (wn + nt * 8 + gid) * STRIDE_BT + kb + tg;
                    b[nt][0] = __float_as_uint(Bs[ib]);
                    b[nt][1] = __float_as_uint(Bs[ib + 4]);
                } else {
                    const int col = wn + nt * 8 + gid;
                    b[nt][0] = __float_as_uint(Bs[(kb + tg) * STRIDE_BN + col]);
                    b[nt][1] = __float_as_uint(Bs[(kb + tg + 4) * STRIDE_BN + col]);
                }
            }
            #pragma unroll
            for (int mt = 0; mt < 4; ++mt) {
                uint32_t a[4];
                const int ia = (wm + mt * 16 + gid) * STRIDE_A + kb + tg;
                a[0] = __float_as_uint(As[ia]);
                a[1] = __float_as_uint(As[ia + 8 * STRIDE_A]);
                a[2] = __float_as_uint(As[ia + 4]);
                a[3] = __float_as_uint(As[ia + 8 * STRIDE_A + 4]);
                #pragma unroll
                for (int nt = 0; nt < 8; ++nt) mma_tf32(acc[mt][nt], a, b[nt]);
            }
        }
    }

    // ---- epilogue ----
    #pragma unroll
    for (int mt = 0; mt < 4; ++mt) {
        const long r0 = m0 + wm + mt * 16 + gid;
        #pragma unroll
        for (int nt = 0; nt < 8; ++nt) {
            const int col = n0 + wn + nt * 8 + 2 * tg;
            float v0 = acc[mt][nt][0] * scale;
            float v1 = acc[mt][nt][1] * scale;
            float v2 = acc[mt][nt][2] * scale;
            float v3 = acc[mt][nt][3] * scale;
            if (BIAS) {
                float b0 = bias[col], b1 = bias[col + 1];
                v0 += b0; v1 += b1; v2 += b0; v3 += b1;
            }
            if (RELU) {
                v0 = fmaxf(v0, 0.0f); v1 = fmaxf(v1, 0.0f);
                v2 = fmaxf(v2, 0.0f); v3 = fmaxf(v3, 0.0f);
            }
            if (ROUND) {
                v0 = f2tf32f(v0); v1 = f2tf32f(v1);
                v2 = f2tf32f(v2); v3 = f2tf32f(v3);
            }
            *(float2*)&C[r0 * (long)N + col]       = make_float2(v0, v1);
            *(float2*)&C[(r0 + 8) * (long)N + col] = make_float2(v2, v3);
        }
    }
}

// ---------------- tf32 pre-round copy ----------------
__global__ void cvt_kernel(const float4* __restrict__ src, float4* __restrict__ dst, int n4)
{
    for (int i = blockIdx.x * blockDim.x + threadIdx.x; i < n4; i += gridDim.x * blockDim.x) {
        float4 v = src[i];
        v.x = f2tf32f(v.x); v.y = f2tf32f(v.y); v.z = f2tf32f(v.z); v.w = f2tf32f(v.w);
        dst[i] = v;
    }
}

// ---------------- row softmax; writes tf32-rounded probs, 0 in masked tail ----------------
__global__ void softmax_kernel(float* __restrict__ S, int Sq, int Sk, int causal)
{
    const long row = blockIdx.x;
    const int  q   = (int)(row % Sq);
    const int  valid = causal ? (q + 1) : Sk;
    float* p = S + row * (long)Sk;
    const int tid = threadIdx.x;
    __shared__ float red[256];

    float m = -3.0e38f;
    for (int k = tid; k < valid; k += 256) m = fmaxf(m, p[k]);
    red[tid] = m; __syncthreads();
    for (int st = 128; st > 0; st >>= 1) {
        if (tid < st) red[tid] = fmaxf(red[tid], red[tid + st]);
        __syncthreads();
    }
    m = red[0]; __syncthreads();

    float s = 0.0f;
    for (int k = tid; k < valid; k += 256) s += __expf(p[k] - m);
    red[tid] = s; __syncthreads();
    for (int st = 128; st > 0; st >>= 1) {
        if (tid < st) red[tid] += red[tid + st];
        __syncthreads();
    }
    const float inv = 1.0f / red[0];

    for (int k = tid; k < Sk; k += 256) {
        float val = (k < valid) ? f2tf32f(__expf(p[k] - m) * inv) : 0.0f;
        p[k] = val;
    }
}

// ---------------- out = LayerNorm(R + X) * gamma + beta ----------------
template<bool ROUND>
__global__ void add_ln_kernel(const float* __restrict__ R, const float* __restrict__ X,
                              const float* __restrict__ g, const float* __restrict__ b,
                              float* __restrict__ O)
{
    const int  tid = threadIdx.x;
    const long row = blockIdx.x;
    const float4 rv = ((const float4*)(R + row * DD))[tid];
    const float4 xv = ((const float4*)(X + row * DD))[tid];
    float v[4] = {rv.x + xv.x, rv.y + xv.y, rv.z + xv.z, rv.w + xv.w};

    float s  = v[0] + v[1] + v[2] + v[3];
    float sq = v[0]*v[0] + v[1]*v[1] + v[2]*v[2] + v[3]*v[3];
    __shared__ float rs[256], rq[256];
    rs[tid] = s; rq[tid] = sq; __syncthreads();
    for (int st = 128; st > 0; st >>= 1) {
        if (tid < st) { rs[tid] += rs[tid + st]; rq[tid] += rq[tid + st]; }
        __syncthreads();
    }
    const float mu  = rs[0] * (1.0f / DD);
    const float var = rq[0] * (1.0f / DD) - mu * mu;
    const float inv = rsqrtf(var + 1e-5f);

    const float4 gv = ((const float4*)g)[tid];
    const float4 bv = ((const float4*)b)[tid];
    float4 o;
    o.x = (v[0] - mu) * inv * gv.x + bv.x;
    o.y = (v[1] - mu) * inv * gv.y + bv.y;
    o.z = (v[2] - mu) * inv * gv.z + bv.z;
    o.w = (v[3] - mu) * inv * gv.w + bv.w;
    if (ROUND) { o.x = f2tf32f(o.x); o.y = f2tf32f(o.y); o.z = f2tf32f(o.z); o.w = f2tf32f(o.w); }
    ((float4*)(O + row * DD))[tid] = o;
}

// ---------------- launch ----------------
extern "C" void kernel_launch(void* const* d_in, const int* in_sizes, int n_in,
                              void* d_out, int out_size)
{
    (void)in_sizes; (void)n_in; (void)out_size;
    const float* y    = (const float*)d_in[0];
    const float* Z    = (const float*)d_in[1];
    const float* Wq1  = (const float*)d_in[2];
    const float* Wk1  = (const float*)d_in[3];
    const float* Wv1  = (const float*)d_in[4];
    const float* Wq2  = (const float*)d_in[5];
    const float* Wk2  = (const float*)d_in[6];
    const float* Wv2  = (const float*)d_in[7];
    const float* Wff1 = (const float*)d_in[8];
    const float* bff1 = (const float*)d_in[9];
    const float* Wff2 = (const float*)d_in[10];
    const float* bff2 = (const float*)d_in[11];
    const float* g1   = (const float*)d_in[12];
    const float* be1  = (const float*)d_in[13];
    const float* g2   = (const float*)d_in[14];
    const float* be2  = (const float*)d_in[15];
    const float* g3   = (const float*)d_in[16];
    const float* be3  = (const float*)d_in[17];
    float* out = (float*)d_out;

    float *W, *Wf1, *Wf2, *yc, *Zc, *QKV, *Sc, *At, *y1, *y2, *H;
    cudaGetSymbolAddress((void**)&W,   g_W);
    cudaGetSymbolAddress((void**)&Wf1, g_Wf1);
    cudaGetSymbolAddress((void**)&Wf2, g_Wf2);
    cudaGetSymbolAddress((void**)&yc,  g_yc);
    cudaGetSymbolAddress((void**)&Zc,  g_Zc);
    cudaGetSymbolAddress((void**)&QKV, g_QKV);
    cudaGetSymbolAddress((void**)&Sc,  g_S);
    cudaGetSymbolAddress((void**)&At,  g_At);
    cudaGetSymbolAddress((void**)&y1,  g_y1);
    cudaGetSymbolAddress((void**)&y2,  g_y2);
    cudaGetSymbolAddress((void**)&H,   g_H);

    cudaFuncSetAttribute(tgemm<false,false,false,false,false,true >, cudaFuncAttributeMaxDynamicSharedMemorySize, SMEM_BYTES);
    cudaFuncSetAttribute(tgemm<true, true, false,false,false,false>, cudaFuncAttributeMaxDynamicSharedMemorySize, SMEM_BYTES);
    cudaFuncSetAttribute(tgemm<true, false,false,false,false,false>, cudaFuncAttributeMaxDynamicSharedMemorySize, SMEM_BYTES);
    cudaFuncSetAttribute(tgemm<false,false,false,false,true, false>, cudaFuncAttributeMaxDynamicSharedMemorySize, SMEM_BYTES);
    cudaFuncSetAttribute(tgemm<false,false,false,false,false,false>, cudaFuncAttributeMaxDynamicSharedMemorySize, SMEM_BYTES);
    cudaFuncSetAttribute(tgemm<false,false,true, true, false,true >, cudaFuncAttributeMaxDynamicSharedMemorySize, SMEM_BYTES);
    cudaFuncSetAttribute(tgemm<false,false,true, false,false,false>, cudaFuncAttributeMaxDynamicSharedMemorySize, SMEM_BYTES);

    // ---- pre-round inputs & weights to canonical tf32 ----
    cvt_kernel<<<1184, 256>>>((const float4*)y,    (float4*)yc,  RD / 4);
    cvt_kernel<<<1184, 256>>>((const float4*)Z,    (float4*)Zc,  RD / 4);
    cvt_kernel<<<296,  256>>>((const float4*)Wq1,  (float4*)(W + 0*DSQ), DSQ / 4);
    cvt_kernel<<<296,  256>>>((const float4*)Wk1,  (float4*)(W + 1*DSQ), DSQ / 4);
    cvt_kernel<<<296,  256>>>((const float4*)Wv1,  (float4*)(W + 2*DSQ), DSQ / 4);
    cvt_kernel<<<296,  256>>>((const float4*)Wq2,  (float4*)(W + 3*DSQ), DSQ / 4);
    cvt_kernel<<<296,  256>>>((const float4*)Wk2,  (float4*)(W + 4*DSQ), DSQ / 4);
    cvt_kernel<<<296,  256>>>((const float4*)Wv2,  (float4*)(W + 5*DSQ), DSQ / 4);
    cvt_kernel<<<1184, 256>>>((const float4*)Wff1, (float4*)Wf1, DD * FFD / 4);
    cvt_kernel<<<1184, 256>>>((const float4*)Wff2, (float4*)Wf2, DD * FFD / 4);

    const dim3 th(256);
    const dim3 gProj3(DD / 256, ROWS / 128, 3);
    const dim3 gProj1(DD / 256, ROWS / 128, 1);
    const dim3 gProj2(DD / 256, ROWS / 128, 2);
    const dim3 gScore(SS / 256, SS / 128, BB);
    const dim3 gAttnV(DD / 256, SS / 128, BB);
    const dim3 gFF1(FFD / 256, ROWS / 128);
    const dim3 gFF2(DD / 256, ROWS / 128);
    const float ascale = 1.0f / 32.0f;            // 1/sqrt(1024)
    const long sQK = (long)SS * DD;
    const long sSc = (long)SS * SS;
    float* Q  = QKV;
    float* Kp = QKV + (long)RD;
    float* V  = QKV + 2L * RD;

    // ---- block 1: causal self-attention + add&norm ----
    tgemm<false,false,false,false,false,true ><<<gProj3, th, SMEM_BYTES>>>(yc, W, nullptr, QKV, DD, DD, 1.0f, 0, DSQ, RD);
    tgemm<true, true, false,false,false,false><<<gScore, th, SMEM_BYTES>>>(Q, Kp, nullptr, Sc, SS, DD, ascale, sQK, sQK, sSc);
    softmax_kernel<<<BB * SS, 256>>>(Sc, SS, SS, 1);
    tgemm<false,false,false,false,true, false><<<gAttnV, th, SMEM_BYTES>>>(Sc, V, nullptr, At, DD, SS, 1.0f, sSc, sQK, sQK);
    add_ln_kernel<true><<<ROWS, 256>>>(y, At, g1, be1, y1);

    // ---- block 2: cross-attention + add&norm ----
    tgemm<false,false,false,false,false,true ><<<gProj1, th, SMEM_BYTES>>>(y1, W + 3L*DSQ, nullptr, Q,  DD, DD, 1.0f, 0, DSQ, RD);
    tgemm<false,false,false,false,false,true ><<<gProj2, th, SMEM_BYTES>>>(Zc, W + 4L*DSQ, nullptr, Kp, DD, DD, 1.0f, 0, DSQ, RD);
    tgemm<true, false,false,false,false,false><<<gScore, th, SMEM_BYTES>>>(Q, Kp, nullptr, Sc, SS, DD, ascale, sQK, sQK, sSc);
    softmax_kernel<<<BB * SS, 256>>>(Sc, SS, SS, 0);
    tgemm<false,false,false,false,false,false><<<gAttnV, th, SMEM_BYTES>>>(Sc, V, nullptr, At, DD, SS, 1.0f, sSc, sQK, sQK);
    add_ln_kernel<true><<<ROWS, 256>>>(y1, At, g2, be2, y2);

    // ---- FFN + add&norm ----
    tgemm<false,false,true, true, false,true ><<<gFF1, th, SMEM_BYTES>>>(y2, Wf1, bff1, H,  FFD, DD,  1.0f, 0, 0, 0);
    tgemm<false,false,true, false,false,false><<<gFF2, th, SMEM_BYTES>>>(H,  Wf2, bff2, At, DD,  FFD, 1.0f, 0, 0, 0);
    add_ln_kernel<false><<<ROWS, 256>>>(y2, At, g3, be3, out);
}